// round 14
// baseline (speedup 1.0000x reference)
#include <cuda_runtime.h>
#include <cuda_bf16.h>
#include <math.h>

// Problem constants
#define T_STEPS 512
#define BATCH   128
#define HDIM    512
#define HDIM3   1536

typedef unsigned long long u64;
typedef unsigned int u32;

// ---------------------------------------------------------------------------
// bf16 helpers
// ---------------------------------------------------------------------------
__device__ __forceinline__ u32 pkbf_(float f0, float f1) {
    unsigned short s0 = __bfloat16_as_ushort(__float2bfloat16_rn(f0));
    unsigned short s1 = __bfloat16_as_ushort(__float2bfloat16_rn(f1));
    return (u32)s0 | ((u32)s1 << 16);
}
__device__ __forceinline__ void split2_(float f0, float f1, u32& hi, u32& lo) {
    __nv_bfloat16 h0 = __float2bfloat16_rn(f0);
    __nv_bfloat16 h1 = __float2bfloat16_rn(f1);
    float r0 = f0 - __bfloat162float(h0);
    float r1 = f1 - __bfloat162float(h1);
    hi = (u32)__bfloat16_as_ushort(h0) | ((u32)__bfloat16_as_ushort(h1) << 16);
    lo = pkbf_(r0, r1);
}

// m16n8k16 bf16 MMA, fp32 accumulate.
__device__ __forceinline__ void mma_bf16(
    float& d0, float& d1, float& d2, float& d3,
    u32 a0, u32 a1, u32 a2, u32 a3, u32 b0, u32 b1)
{
    asm volatile(
        "mma.sync.aligned.m16n8k16.row.col.f32.bf16.bf16.f32 "
        "{%0,%1,%2,%3}, {%4,%5,%6,%7}, {%8,%9}, {%0,%1,%2,%3};"
        : "+f"(d0), "+f"(d1), "+f"(d2), "+f"(d3)
        : "r"(a0), "r"(a1), "r"(a2), "r"(a3), "r"(b0), "r"(b1));
}

// ---------------------------------------------------------------------------
// Scratch + barrier state
// ---------------------------------------------------------------------------
#define KP_TOTAL 256   // 512 k / 2 per pair
__device__ __align__(16) float g_gi[(size_t)T_STEPS * BATCH * HDIM3];
__device__ __align__(16) u64 g_h2[2][KP_TOTAL * BATCH];
__device__ unsigned int g_arrive = 0;
__device__ unsigned int g_release = 0;

#define SCAN_BLOCKS 64

// Lean sense-reversing grid barrier (acq_rel semantics; validated R13).
__device__ __forceinline__ void grid_barrier(int nblk) {
    __syncthreads();
    if (threadIdx.x == 0) {
        unsigned gen;
        asm volatile("ld.acquire.gpu.u32 %0, [%1];"
                     : "=r"(gen) : "l"(&g_release) : "memory");
        unsigned ticket;
        asm volatile("atom.acq_rel.gpu.add.u32 %0, [%1], 1;"
                     : "=r"(ticket) : "l"(&g_arrive) : "memory");
        if (ticket == (unsigned)(nblk - 1)) {
            asm volatile("st.relaxed.gpu.u32 [%0], 0;"
                         :: "l"(&g_arrive) : "memory");
            unsigned dummy;
            asm volatile("atom.release.gpu.add.u32 %0, [%1], 1;"
                         : "=r"(dummy) : "l"(&g_release) : "memory");
        } else {
            unsigned r;
            while (1) {
                asm volatile("ld.acquire.gpu.u32 %0, [%1];"
                             : "=r"(r) : "l"(&g_release) : "memory");
                if (r != gen) break;
                __nanosleep(16);
            }
        }
    }
    __syncthreads();
}

// ---------------------------------------------------------------------------
// Pre-GEMM (bf16 3-term compensated MMA): gi = x @ Wi + bi.  (validated R13)
// ---------------------------------------------------------------------------
#define GSTRIDE 132

__global__ __launch_bounds__(256) void gemm_gi_tc_kernel(
    const float* __restrict__ X, const float* __restrict__ Wi,
    const float* __restrict__ bi, float* __restrict__ gi)
{
    __shared__ __align__(16) u64 Xs[8 * GSTRIDE];
    __shared__ __align__(16) u64 Ws[8 * GSTRIDE];

    const int m0 = blockIdx.y * 128;
    const int n0 = blockIdx.x * 128;
    const int tid = threadIdx.x;
    const int wid = tid >> 5;
    const int lane = tid & 31;
    const int g = lane >> 2;
    const int tig = lane & 3;
    const int wm = (wid & 3) * 32;
    const int wn = (wid >> 2) * 64;

    const int xr = tid >> 1;
    const int xc = (tid & 1) * 8;
    const int wkp = tid >> 5;
    const int nb = (lane) * 4;

    float acc[2][8][4];
#pragma unroll
    for (int mf = 0; mf < 2; mf++)
#pragma unroll
        for (int nf = 0; nf < 8; nf++)
#pragma unroll
            for (int r = 0; r < 4; r++) acc[mf][nf][r] = 0.f;

    for (int k0 = 0; k0 < HDIM; k0 += 16) {
#pragma unroll
        for (int h = 0; h < 2; h++) {
            float4 v = *(const float4*)&X[(size_t)(m0 + xr) * HDIM + k0 + xc + h * 4];
            u32 hi0, lo0, hi1, lo1;
            split2_(v.x, v.y, hi0, lo0);
            split2_(v.z, v.w, hi1, lo1);
            Xs[(xc / 2 + h * 2 + 0) * GSTRIDE + xr] = (u64)hi0 | ((u64)lo0 << 32);
            Xs[(xc / 2 + h * 2 + 1) * GSTRIDE + xr] = (u64)hi1 | ((u64)lo1 << 32);
        }
        {
            float4 r0 = *(const float4*)&Wi[(size_t)(k0 + 2 * wkp) * HDIM3 + n0 + nb];
            float4 r1 = *(const float4*)&Wi[(size_t)(k0 + 2 * wkp + 1) * HDIM3 + n0 + nb];
            float a0[4] = {r0.x, r0.y, r0.z, r0.w};
            float a1[4] = {r1.x, r1.y, r1.z, r1.w};
#pragma unroll
            for (int i = 0; i < 4; i++) {
                u32 hi, lo;
                split2_(a0[i], a1[i], hi, lo);
                Ws[wkp * GSTRIDE + nb + i] = (u64)hi | ((u64)lo << 32);
            }
        }
        __syncthreads();

        u32 ah[2][4], al[2][4];
#pragma unroll
        for (int mf = 0; mf < 2; mf++) {
            int mr = wm + mf * 16 + g;
            u64 d0 = Xs[tig * GSTRIDE + mr];
            u64 d1 = Xs[tig * GSTRIDE + mr + 8];
            u64 d2 = Xs[(tig + 4) * GSTRIDE + mr];
            u64 d3 = Xs[(tig + 4) * GSTRIDE + mr + 8];
            ah[mf][0] = (u32)d0; al[mf][0] = (u32)(d0 >> 32);
            ah[mf][1] = (u32)d1; al[mf][1] = (u32)(d1 >> 32);
            ah[mf][2] = (u32)d2; al[mf][2] = (u32)(d2 >> 32);
            ah[mf][3] = (u32)d3; al[mf][3] = (u32)(d3 >> 32);
        }
#pragma unroll
        for (int nf = 0; nf < 8; nf++) {
            int nc = wn + nf * 8 + g;
            u64 e0 = Ws[tig * GSTRIDE + nc];
            u64 e1 = Ws[(tig + 4) * GSTRIDE + nc];
            u32 bh0 = (u32)e0, bl0 = (u32)(e0 >> 32);
            u32 bh1 = (u32)e1, bl1 = (u32)(e1 >> 32);
#pragma unroll
            for (int mf = 0; mf < 2; mf++) {
                mma_bf16(acc[mf][nf][0], acc[mf][nf][1], acc[mf][nf][2], acc[mf][nf][3],
                         ah[mf][0], ah[mf][1], ah[mf][2], ah[mf][3], bh0, bh1);
                mma_bf16(acc[mf][nf][0], acc[mf][nf][1], acc[mf][nf][2], acc[mf][nf][3],
                         ah[mf][0], ah[mf][1], ah[mf][2], ah[mf][3], bl0, bl1);
                mma_bf16(acc[mf][nf][0], acc[mf][nf][1], acc[mf][nf][2], acc[mf][nf][3],
                         al[mf][0], al[mf][1], al[mf][2], al[mf][3], bh0, bh1);
            }
        }
        __syncthreads();
    }

#pragma unroll
    for (int mf = 0; mf < 2; mf++) {
#pragma unroll
        for (int nf = 0; nf < 8; nf++) {
            int n = n0 + wn + nf * 8 + 2 * tig;
            float b0v = bi[n], b1v = bi[n + 1];
            int mA = m0 + wm + mf * 16 + g;
            int mB = mA + 8;
            *(float2*)&gi[(size_t)mA * HDIM3 + n] =
                make_float2(acc[mf][nf][0] + b0v, acc[mf][nf][1] + b1v);
            *(float2*)&gi[(size_t)mB * HDIM3 + n] =
                make_float2(acc[mf][nf][2] + b0v, acc[mf][nf][3] + b1v);
        }
    }
}

// ---------------------------------------------------------------------------
// Persistent scan: 64 blocks x 256 threads (8 warps x 16 batch rows).
// Block owns h-cols j0..j0+7 => 24 Wh cols = 3 n-frags: nf0=r, nf1=z, nf2=n.
// C-layout makes gates LANE-LOCAL: lane (g,tig) holds, for rows g and g+8,
// cols 2tig..2tig+1 of each gate in acc[nf][0..3]. No shuffle, no smem dump.
// Bs: 256 kp x stride 28 u64 = 56 KB (< 64 KB static limit; conflict-free:
// per 16-lane phase banks {0,24,16,8}+2g all distinct).
// ---------------------------------------------------------------------------
#define SCAN_THREADS 256
#define JCH 8
#define BS_STRIDE 28      // u64
#define PD 4              // prefetch depth (ring)

__device__ __forceinline__ float fast_sigmoid(float x) {
    return 1.0f / (1.0f + __expf(-x));
}
__device__ __forceinline__ float fast_tanh(float x) {
    return 2.0f / (1.0f + __expf(-2.0f * x)) - 1.0f;
}

__global__ __launch_bounds__(SCAN_THREADS) void scan_kernel(
    const float* __restrict__ h0, const float* __restrict__ Wh,
    const float* __restrict__ bhn,
    float* __restrict__ out_h, float* __restrict__ out_ys)
{
    __shared__ __align__(16) u64 Bs[KP_TOTAL * BS_STRIDE];   // 56 KB

    const int tid = threadIdx.x;
    const int wid = tid >> 5;
    const int lane = tid & 31;
    const int g = lane >> 2;
    const int tig = lane & 3;
    const int j0 = blockIdx.x * JCH;

    // --- One-time: Wh slice -> bf16-split k-pair fragments in SMEM ---
    {
        int kp = tid;  // 256 threads, 256 k-pairs
        for (int c = 0; c < 24; c++) {
            int col = (c >> 3) * HDIM + j0 + (c & 7);
            float w0 = Wh[(size_t)(2 * kp) * HDIM3 + col];
            float w1 = Wh[(size_t)(2 * kp + 1) * HDIM3 + col];
            u32 hi, lo;
            split2_(w0, w1, hi, lo);
            Bs[kp * BS_STRIDE + c] = (u64)hi | ((u64)lo << 32);
        }
    }

    // Lane's assignment: rows rA = mbase+g, rB = rA+8; cols jcol..jcol+1.
    const int mbase = wid * 16;
    const int rA = mbase + g;
    const int rB = rA + 8;
    const int jcol = j0 + 2 * tig;
    const int kp_out = j0 / 2 + tig;

    float bn0 = bhn[jcol], bn1 = bhn[jcol + 1];
    float hA0, hA1, hB0, hB1;
    {
        float2 vA = *(const float2*)&h0[(size_t)rA * HDIM + jcol];
        float2 vB = *(const float2*)&h0[(size_t)rB * HDIM + jcol];
        hA0 = vA.x; hA1 = vA.y; hB0 = vB.x; hB1 = vB.y;
        u32 hi, lo;
        split2_(hA0, hA1, hi, lo);
        g_h2[0][kp_out * BATCH + rA] = (u64)hi | ((u64)lo << 32);
        split2_(hB0, hB1, hi, lo);
        g_h2[0][kp_out * BATCH + rB] = (u64)hi | ((u64)lo << 32);
    }
    grid_barrier(SCAN_BLOCKS);

    for (int t = 0; t < T_STEPS; t++) {
        const u64* __restrict__ hp = g_h2[t & 1];

        // early gi loads (lane's own 2 rows x 2 cols x 3 gates)
        const float* giA = &g_gi[((size_t)t * BATCH + rA) * HDIM3 + jcol];
        const float* giB = &g_gi[((size_t)t * BATCH + rB) * HDIM3 + jcol];
        float2 grA = *(const float2*)giA;
        float2 gzA = *(const float2*)(giA + HDIM);
        float2 gnA = *(const float2*)(giA + 2 * HDIM);
        float2 grB = *(const float2*)giB;
        float2 gzB = *(const float2*)(giB + HDIM);
        float2 gnB = *(const float2*)(giB + 2 * HDIM);

        float acc[3][4];
#pragma unroll
        for (int nf = 0; nf < 3; nf++)
#pragma unroll
            for (int r = 0; r < 4; r++) acc[nf][r] = 0.f;

        // A-frag prefetch ring, depth PD=4.
        u64 pa[PD][4];
#pragma unroll
        for (int p = 0; p < PD; p++) {
            int ix = (p * 8 + tig) * BATCH + mbase + g;
            pa[p][0] = hp[ix];       pa[p][1] = hp[ix + 8];
            pa[p][2] = hp[ix + 512]; pa[p][3] = hp[ix + 520];
        }

#pragma unroll 4
        for (int kt = 0; kt < 32; kt++) {
            const int s = kt & (PD - 1);
            u64 d0 = pa[s][0], d1 = pa[s][1], d2 = pa[s][2], d3 = pa[s][3];
            if (kt + PD < 32) {
                int ix = ((kt + PD) * 8 + tig) * BATCH + mbase + g;
                pa[s][0] = hp[ix];       pa[s][1] = hp[ix + 8];
                pa[s][2] = hp[ix + 512]; pa[s][3] = hp[ix + 520];
            }
            u32 ah0 = (u32)d0, al0 = (u32)(d0 >> 32);
            u32 ah1 = (u32)d1, al1 = (u32)(d1 >> 32);
            u32 ah2 = (u32)d2, al2 = (u32)(d2 >> 32);
            u32 ah3 = (u32)d3, al3 = (u32)(d3 >> 32);
#pragma unroll
            for (int nf = 0; nf < 3; nf++) {
                u64 e0 = Bs[(kt * 8 + tig) * BS_STRIDE + nf * 8 + g];
                u64 e1 = Bs[(kt * 8 + tig + 4) * BS_STRIDE + nf * 8 + g];
                u32 bh0 = (u32)e0, bl0 = (u32)(e0 >> 32);
                u32 bh1 = (u32)e1, bl1 = (u32)(e1 >> 32);
                mma_bf16(acc[nf][0], acc[nf][1], acc[nf][2], acc[nf][3],
                         ah0, ah1, ah2, ah3, bh0, bh1);
                mma_bf16(acc[nf][0], acc[nf][1], acc[nf][2], acc[nf][3],
                         ah0, ah1, ah2, ah3, bl0, bl1);
                mma_bf16(acc[nf][0], acc[nf][1], acc[nf][2], acc[nf][3],
                         al0, al1, al2, al3, bh0, bh1);
            }
        }

        // Lane-local gates: acc[0]=r, acc[1]=z, acc[2]=n;
        // c0/c1 = row rA, c2/c3 = row rB.
        {
            float r0 = fast_sigmoid(grA.x + acc[0][0]);
            float r1 = fast_sigmoid(grA.y + acc[0][1]);
            float z0 = fast_sigmoid(gzA.x + acc[1][0]);
            float z1 = fast_sigmoid(gzA.y + acc[1][1]);
            float n0 = fast_tanh(gnA.x + r0 * (acc[2][0] + bn0));
            float n1 = fast_tanh(gnA.y + r1 * (acc[2][1] + bn1));
            hA0 = (1.0f - z0) * n0 + z0 * hA0;
            hA1 = (1.0f - z1) * n1 + z1 * hA1;
        }
        {
            float r0 = fast_sigmoid(grB.x + acc[0][2]);
            float r1 = fast_sigmoid(grB.y + acc[0][3]);
            float z0 = fast_sigmoid(gzB.x + acc[1][2]);
            float z1 = fast_sigmoid(gzB.y + acc[1][3]);
            float n0 = fast_tanh(gnB.x + r0 * (acc[2][2] + bn0));
            float n1 = fast_tanh(gnB.y + r1 * (acc[2][3] + bn1));
            hB0 = (1.0f - z0) * n0 + z0 * hB0;
            hB1 = (1.0f - z1) * n1 + z1 * hB1;
        }

        *(float2*)&out_ys[((size_t)t * BATCH + rA) * HDIM + jcol] =
            make_float2(hA0, hA1);
        *(float2*)&out_ys[((size_t)t * BATCH + rB) * HDIM + jcol] =
            make_float2(hB0, hB1);

        {
            u64* __restrict__ hq = g_h2[(t & 1) ^ 1];
            u32 hi, lo;
            split2_(hA0, hA1, hi, lo);
            hq[kp_out * BATCH + rA] = (u64)hi | ((u64)lo << 32);
            split2_(hB0, hB1, hi, lo);
            hq[kp_out * BATCH + rB] = (u64)hi | ((u64)lo << 32);
        }

        grid_barrier(SCAN_BLOCKS);
    }

    if (out_h) {
        *(float2*)&out_h[(size_t)rA * HDIM + jcol] = make_float2(hA0, hA1);
        *(float2*)&out_h[(size_t)rB * HDIM + jcol] = make_float2(hB0, hB1);
    }
}

// ---------------------------------------------------------------------------
// kernel_launch: inputs per metadata order: x, h0, Wi, bi, Wh, bhn
// ---------------------------------------------------------------------------
extern "C" void kernel_launch(void* const* d_in, const int* in_sizes, int n_in,
                              void* d_out, int out_size)
{
    const float* x   = (const float*)d_in[0];   // [T, B, H]
    const float* h0  = (const float*)d_in[1];   // [B, H]
    const float* Wi  = (const float*)d_in[2];   // [H, 3H]
    const float* bi  = (const float*)d_in[3];   // [3H]
    const float* Wh  = (const float*)d_in[4];   // [H, 3H]
    const float* bhn = (const float*)d_in[5];   // [H]

    float* out = (float*)d_out;
    float* out_h;
    float* out_ys;
    const long long ys_elems = (long long)T_STEPS * BATCH * HDIM;
    if ((long long)out_size >= ys_elems + (long long)BATCH * HDIM) {
        out_h = out;                    // (h_final, ys) flattened in order
        out_ys = out + (size_t)BATCH * HDIM;
    } else {
        out_h = nullptr;                // ys only
        out_ys = out;
    }

    float* gi;
    cudaGetSymbolAddress((void**)&gi, g_gi);

    // 1) gi = x @ Wi + bi  (bf16 3-term compensated tensor-core GEMM)
    dim3 ggrid(HDIM3 / 128, (T_STEPS * BATCH) / 128);
    gemm_gi_tc_kernel<<<ggrid, 256>>>(x, Wi, bi, gi);

    // 2) persistent GRU scan (64 blocks x 8 cols, lane-local gate epilogue)
    scan_kernel<<<SCAN_BLOCKS, SCAN_THREADS>>>(h0, Wh, bhn, out_h, out_ys);
}

// round 15
// speedup vs baseline: 1.0984x; 1.0984x over previous
#include <cuda_runtime.h>
#include <cuda_bf16.h>
#include <math.h>

// Problem constants
#define T_STEPS 512
#define BATCH   128
#define HDIM    512
#define HDIM3   1536

typedef unsigned long long u64;
typedef unsigned int u32;

// ---------------------------------------------------------------------------
// bf16 helpers
// ---------------------------------------------------------------------------
__device__ __forceinline__ u32 pkbf_(float f0, float f1) {
    unsigned short s0 = __bfloat16_as_ushort(__float2bfloat16_rn(f0));
    unsigned short s1 = __bfloat16_as_ushort(__float2bfloat16_rn(f1));
    return (u32)s0 | ((u32)s1 << 16);
}
__device__ __forceinline__ void split2_(float f0, float f1, u32& hi, u32& lo) {
    __nv_bfloat16 h0 = __float2bfloat16_rn(f0);
    __nv_bfloat16 h1 = __float2bfloat16_rn(f1);
    float r0 = f0 - __bfloat162float(h0);
    float r1 = f1 - __bfloat162float(h1);
    hi = (u32)__bfloat16_as_ushort(h0) | ((u32)__bfloat16_as_ushort(h1) << 16);
    lo = pkbf_(r0, r1);
}

// m16n8k16 bf16 MMA, fp32 accumulate.
__device__ __forceinline__ void mma_bf16(
    float& d0, float& d1, float& d2, float& d3,
    u32 a0, u32 a1, u32 a2, u32 a3, u32 b0, u32 b1)
{
    asm volatile(
        "mma.sync.aligned.m16n8k16.row.col.f32.bf16.bf16.f32 "
        "{%0,%1,%2,%3}, {%4,%5,%6,%7}, {%8,%9}, {%0,%1,%2,%3};"
        : "+f"(d0), "+f"(d1), "+f"(d2), "+f"(d3)
        : "r"(a0), "r"(a1), "r"(a2), "r"(a3), "r"(b0), "r"(b1));
}

// ---------------------------------------------------------------------------
// Scratch + barrier state
// ---------------------------------------------------------------------------
#define KP_TOTAL 256   // 512 k / 2 per pair
__device__ __align__(16) float g_gi[(size_t)T_STEPS * BATCH * HDIM3];
__device__ __align__(16) u64 g_h2[2][KP_TOTAL * BATCH];
__device__ unsigned int g_arrive = 0;
__device__ unsigned int g_release = 0;

#define SCAN_BLOCKS 128

// Lean sense-reversing grid barrier (acq_rel semantics; validated R13).
__device__ __forceinline__ void grid_barrier(int nblk) {
    __syncthreads();
    if (threadIdx.x == 0) {
        unsigned gen;
        asm volatile("ld.acquire.gpu.u32 %0, [%1];"
                     : "=r"(gen) : "l"(&g_release) : "memory");
        unsigned ticket;
        asm volatile("atom.acq_rel.gpu.add.u32 %0, [%1], 1;"
                     : "=r"(ticket) : "l"(&g_arrive) : "memory");
        if (ticket == (unsigned)(nblk - 1)) {
            asm volatile("st.relaxed.gpu.u32 [%0], 0;"
                         :: "l"(&g_arrive) : "memory");
            unsigned dummy;
            asm volatile("atom.release.gpu.add.u32 %0, [%1], 1;"
                         : "=r"(dummy) : "l"(&g_release) : "memory");
        } else {
            unsigned r;
            while (1) {
                asm volatile("ld.acquire.gpu.u32 %0, [%1];"
                             : "=r"(r) : "l"(&g_release) : "memory");
                if (r != gen) break;
                __nanosleep(16);
            }
        }
    }
    __syncthreads();
}

// ---------------------------------------------------------------------------
// Pre-GEMM (bf16 3-term compensated MMA): gi = x @ Wi + bi.  (validated R13)
// ---------------------------------------------------------------------------
#define GSTRIDE 132

__global__ __launch_bounds__(256) void gemm_gi_tc_kernel(
    const float* __restrict__ X, const float* __restrict__ Wi,
    const float* __restrict__ bi, float* __restrict__ gi)
{
    __shared__ __align__(16) u64 Xs[8 * GSTRIDE];
    __shared__ __align__(16) u64 Ws[8 * GSTRIDE];

    const int m0 = blockIdx.y * 128;
    const int n0 = blockIdx.x * 128;
    const int tid = threadIdx.x;
    const int wid = tid >> 5;
    const int lane = tid & 31;
    const int g = lane >> 2;
    const int tig = lane & 3;
    const int wm = (wid & 3) * 32;
    const int wn = (wid >> 2) * 64;

    const int xr = tid >> 1;
    const int xc = (tid & 1) * 8;
    const int wkp = tid >> 5;
    const int nb = (lane) * 4;

    float acc[2][8][4];
#pragma unroll
    for (int mf = 0; mf < 2; mf++)
#pragma unroll
        for (int nf = 0; nf < 8; nf++)
#pragma unroll
            for (int r = 0; r < 4; r++) acc[mf][nf][r] = 0.f;

    for (int k0 = 0; k0 < HDIM; k0 += 16) {
#pragma unroll
        for (int h = 0; h < 2; h++) {
            float4 v = *(const float4*)&X[(size_t)(m0 + xr) * HDIM + k0 + xc + h * 4];
            u32 hi0, lo0, hi1, lo1;
            split2_(v.x, v.y, hi0, lo0);
            split2_(v.z, v.w, hi1, lo1);
            Xs[(xc / 2 + h * 2 + 0) * GSTRIDE + xr] = (u64)hi0 | ((u64)lo0 << 32);
            Xs[(xc / 2 + h * 2 + 1) * GSTRIDE + xr] = (u64)hi1 | ((u64)lo1 << 32);
        }
        {
            float4 r0 = *(const float4*)&Wi[(size_t)(k0 + 2 * wkp) * HDIM3 + n0 + nb];
            float4 r1 = *(const float4*)&Wi[(size_t)(k0 + 2 * wkp + 1) * HDIM3 + n0 + nb];
            float a0[4] = {r0.x, r0.y, r0.z, r0.w};
            float a1[4] = {r1.x, r1.y, r1.z, r1.w};
#pragma unroll
            for (int i = 0; i < 4; i++) {
                u32 hi, lo;
                split2_(a0[i], a1[i], hi, lo);
                Ws[wkp * GSTRIDE + nb + i] = (u64)hi | ((u64)lo << 32);
            }
        }
        __syncthreads();

        u32 ah[2][4], al[2][4];
#pragma unroll
        for (int mf = 0; mf < 2; mf++) {
            int mr = wm + mf * 16 + g;
            u64 d0 = Xs[tig * GSTRIDE + mr];
            u64 d1 = Xs[tig * GSTRIDE + mr + 8];
            u64 d2 = Xs[(tig + 4) * GSTRIDE + mr];
            u64 d3 = Xs[(tig + 4) * GSTRIDE + mr + 8];
            ah[mf][0] = (u32)d0; al[mf][0] = (u32)(d0 >> 32);
            ah[mf][1] = (u32)d1; al[mf][1] = (u32)(d1 >> 32);
            ah[mf][2] = (u32)d2; al[mf][2] = (u32)(d2 >> 32);
            ah[mf][3] = (u32)d3; al[mf][3] = (u32)(d3 >> 32);
        }
#pragma unroll
        for (int nf = 0; nf < 8; nf++) {
            int nc = wn + nf * 8 + g;
            u64 e0 = Ws[tig * GSTRIDE + nc];
            u64 e1 = Ws[(tig + 4) * GSTRIDE + nc];
            u32 bh0 = (u32)e0, bl0 = (u32)(e0 >> 32);
            u32 bh1 = (u32)e1, bl1 = (u32)(e1 >> 32);
#pragma unroll
            for (int mf = 0; mf < 2; mf++) {
                mma_bf16(acc[mf][nf][0], acc[mf][nf][1], acc[mf][nf][2], acc[mf][nf][3],
                         ah[mf][0], ah[mf][1], ah[mf][2], ah[mf][3], bh0, bh1);
                mma_bf16(acc[mf][nf][0], acc[mf][nf][1], acc[mf][nf][2], acc[mf][nf][3],
                         ah[mf][0], ah[mf][1], ah[mf][2], ah[mf][3], bl0, bl1);
                mma_bf16(acc[mf][nf][0], acc[mf][nf][1], acc[mf][nf][2], acc[mf][nf][3],
                         al[mf][0], al[mf][1], al[mf][2], al[mf][3], bh0, bh1);
            }
        }
        __syncthreads();
    }

#pragma unroll
    for (int mf = 0; mf < 2; mf++) {
#pragma unroll
        for (int nf = 0; nf < 8; nf++) {
            int n = n0 + wn + nf * 8 + 2 * tig;
            float b0v = bi[n], b1v = bi[n + 1];
            int mA = m0 + wm + mf * 16 + g;
            int mB = mA + 8;
            *(float2*)&gi[(size_t)mA * HDIM3 + n] =
                make_float2(acc[mf][nf][0] + b0v, acc[mf][nf][1] + b1v);
            *(float2*)&gi[(size_t)mB * HDIM3 + n] =
                make_float2(acc[mf][nf][2] + b0v, acc[mf][nf][3] + b1v);
        }
    }
}

// ---------------------------------------------------------------------------
// Persistent scan (R13 structure; 128 blocks x 256 threads, shuffle gates).
// ONE change vs R13: each of the 3 compensation terms gets its OWN
// accumulator (accT[3][2][4]) -> dependency chain per accumulator drops
// 96 -> 32 chained HMMAs, ILP 2 -> 6. Exact same math (terms summed after).
// ---------------------------------------------------------------------------
#define SCAN_THREADS 256
#define BS_STRIDE 20      // u64; conflict-free B-frag loads
#define PD 4              // prefetch depth (ring)

__device__ __forceinline__ float fast_sigmoid(float x) {
    return 1.0f / (1.0f + __expf(-x));
}
__device__ __forceinline__ float fast_tanh(float x) {
    return 2.0f / (1.0f + __expf(-2.0f * x)) - 1.0f;
}

__global__ __launch_bounds__(SCAN_THREADS) void scan_kernel(
    const float* __restrict__ h0, const float* __restrict__ Wh,
    const float* __restrict__ bhn,
    float* __restrict__ out_h, float* __restrict__ out_ys)
{
    __shared__ __align__(16) u64 Bs[KP_TOTAL * BS_STRIDE];   // 40 KB

    const int tid = threadIdx.x;
    const int wid = tid >> 5;
    const int lane = tid & 31;
    const int g = lane >> 2;
    const int tig = lane & 3;
    const int j0 = blockIdx.x * 4;

    // --- One-time: Wh slice -> bf16-split k-pair fragments in SMEM ---
    {
        int kp = tid;  // 256 threads, 256 k-pairs
#pragma unroll
        for (int n = 12; n < 16; n++) Bs[kp * BS_STRIDE + n] = 0ull;
        for (int c = 0; c < 12; c++) {
            int col = (c >> 2) * HDIM + j0 + (c & 3);
            float w0 = Wh[(size_t)(2 * kp) * HDIM3 + col];
            float w1 = Wh[(size_t)(2 * kp + 1) * HDIM3 + col];
            u32 hi, lo;
            split2_(w0, w1, hi, lo);
            Bs[kp * BS_STRIDE + c] = (u64)hi | ((u64)lo << 32);
        }
    }

    // Lane's gate assignment
    const int row = wid * 16 + g + ((tig & 2) << 2);  // +8 for tig>=2
    const int jc = (tig & 1) * 2;                     // col pair base (0 or 2)
    const int jcol = j0 + jc;
    const int kp_out = j0 / 2 + (tig & 1);

    float bn0 = bhn[jcol], bn1 = bhn[jcol + 1];
    float hn0, hn1;
    {
        float2 v = *(const float2*)&h0[(size_t)row * HDIM + jcol];
        hn0 = v.x; hn1 = v.y;
        u32 hi, lo;
        split2_(hn0, hn1, hi, lo);
        g_h2[0][kp_out * BATCH + row] = (u64)hi | ((u64)lo << 32);
    }
    grid_barrier(SCAN_BLOCKS);

    const int mbase = wid * 16;   // warp's batch-row base for MMA

    for (int t = 0; t < T_STEPS; t++) {
        const u64* __restrict__ hp = g_h2[t & 1];

        // early gi loads (this lane's own 2 gate columns, 3 gates)
        const float* gip = &g_gi[((size_t)t * BATCH + row) * HDIM3 + jcol];
        float2 gr = *(const float2*)gip;
        float2 gz = *(const float2*)(gip + HDIM);
        float2 gn = *(const float2*)(gip + 2 * HDIM);

        // Per-term accumulators: 6 independent HMMA chains of length 32.
        float accT[3][2][4];
#pragma unroll
        for (int tm = 0; tm < 3; tm++)
#pragma unroll
            for (int nf = 0; nf < 2; nf++)
#pragma unroll
                for (int r = 0; r < 4; r++) accT[tm][nf][r] = 0.f;

        // A-frag prefetch ring, depth PD=4.
        u64 pa[PD][4];
#pragma unroll
        for (int p = 0; p < PD; p++) {
            int ix = (p * 8 + tig) * BATCH + mbase + g;
            pa[p][0] = hp[ix];       pa[p][1] = hp[ix + 8];
            pa[p][2] = hp[ix + 512]; pa[p][3] = hp[ix + 520];
        }

#pragma unroll 4
        for (int kt = 0; kt < 32; kt++) {
            const int s = kt & (PD - 1);
            u64 d0 = pa[s][0], d1 = pa[s][1], d2 = pa[s][2], d3 = pa[s][3];
            if (kt + PD < 32) {
                int ix = ((kt + PD) * 8 + tig) * BATCH + mbase + g;
                pa[s][0] = hp[ix];       pa[s][1] = hp[ix + 8];
                pa[s][2] = hp[ix + 512]; pa[s][3] = hp[ix + 520];
            }
            u32 ah0 = (u32)d0, al0 = (u32)(d0 >> 32);
            u32 ah1 = (u32)d1, al1 = (u32)(d1 >> 32);
            u32 ah2 = (u32)d2, al2 = (u32)(d2 >> 32);
            u32 ah3 = (u32)d3, al3 = (u32)(d3 >> 32);
#pragma unroll
            for (int nf = 0; nf < 2; nf++) {
                u64 e0 = Bs[(kt * 8 + tig) * BS_STRIDE + nf * 8 + g];
                u64 e1 = Bs[(kt * 8 + tig + 4) * BS_STRIDE + nf * 8 + g];
                u32 bh0 = (u32)e0, bl0 = (u32)(e0 >> 32);
                u32 bh1 = (u32)e1, bl1 = (u32)(e1 >> 32);
                mma_bf16(accT[0][nf][0], accT[0][nf][1], accT[0][nf][2], accT[0][nf][3],
                         ah0, ah1, ah2, ah3, bh0, bh1);
                mma_bf16(accT[1][nf][0], accT[1][nf][1], accT[1][nf][2], accT[1][nf][3],
                         ah0, ah1, ah2, ah3, bl0, bl1);
                mma_bf16(accT[2][nf][0], accT[2][nf][1], accT[2][nf][2], accT[2][nf][3],
                         al0, al1, al2, al3, bh0, bh1);
            }
        }

        // Sum the three terms (exact: same values, different association).
        float acc[2][4];
#pragma unroll
        for (int nf = 0; nf < 2; nf++)
#pragma unroll
            for (int c = 0; c < 4; c++)
                acc[nf][c] = accT[0][nf][c] + (accT[1][nf][c] + accT[2][nf][c]);

        // Fragment exchange: partner lane = lane XOR 2 (tig0<->tig2, 1<->3).
        float sh0[4], sh1[4];
#pragma unroll
        for (int c = 0; c < 4; c++) {
            sh0[c] = __shfl_xor_sync(0xFFFFFFFFu, acc[0][c], 2);
            sh1[c] = __shfl_xor_sync(0xFFFFFFFFu, acc[1][c], 2);
        }

        float rin0, rin1, zin0, zin1, nin0, nin1;
        if ((tig & 2) == 0) {
            rin0 = acc[0][0]; rin1 = acc[0][1];
            zin0 = sh0[0];    zin1 = sh0[1];
            nin0 = acc[1][0]; nin1 = acc[1][1];
        } else {
            rin0 = sh0[2];    rin1 = sh0[3];
            zin0 = acc[0][2]; zin1 = acc[0][3];
            nin0 = sh1[2];    nin1 = sh1[3];
        }

        {
            float r0 = fast_sigmoid(gr.x + rin0);
            float r1 = fast_sigmoid(gr.y + rin1);
            float z0 = fast_sigmoid(gz.x + zin0);
            float z1 = fast_sigmoid(gz.y + zin1);
            float n0 = fast_tanh(gn.x + r0 * (nin0 + bn0));
            float n1 = fast_tanh(gn.y + r1 * (nin1 + bn1));
            hn0 = (1.0f - z0) * n0 + z0 * hn0;
            hn1 = (1.0f - z1) * n1 + z1 * hn1;
        }

        *(float2*)&out_ys[((size_t)t * BATCH + row) * HDIM + jcol] =
            make_float2(hn0, hn1);

        {
            u64* __restrict__ hq = g_h2[(t & 1) ^ 1];
            u32 hi, lo;
            split2_(hn0, hn1, hi, lo);
            hq[kp_out * BATCH + row] = (u64)hi | ((u64)lo << 32);
        }

        grid_barrier(SCAN_BLOCKS);
    }

    if (out_h) {
        *(float2*)&out_h[(size_t)row * HDIM + jcol] = make_float2(hn0, hn1);
    }
}

// ---------------------------------------------------------------------------
// kernel_launch: inputs per metadata order: x, h0, Wi, bi, Wh, bhn
// ---------------------------------------------------------------------------
extern "C" void kernel_launch(void* const* d_in, const int* in_sizes, int n_in,
                              void* d_out, int out_size)
{
    const float* x   = (const float*)d_in[0];   // [T, B, H]
    const float* h0  = (const float*)d_in[1];   // [B, H]
    const float* Wi  = (const float*)d_in[2];   // [H, 3H]
    const float* bi  = (const float*)d_in[3];   // [3H]
    const float* Wh  = (const float*)d_in[4];   // [H, 3H]
    const float* bhn = (const float*)d_in[5];   // [H]

    float* out = (float*)d_out;
    float* out_h;
    float* out_ys;
    const long long ys_elems = (long long)T_STEPS * BATCH * HDIM;
    if ((long long)out_size >= ys_elems + (long long)BATCH * HDIM) {
        out_h = out;                    // (h_final, ys) flattened in order
        out_ys = out + (size_t)BATCH * HDIM;
    } else {
        out_h = nullptr;                // ys only
        out_ys = out;
    }

    float* gi;
    cudaGetSymbolAddress((void**)&gi, g_gi);

    // 1) gi = x @ Wi + bi  (bf16 3-term compensated tensor-core GEMM)
    dim3 ggrid(HDIM3 / 128, (T_STEPS * BATCH) / 128);
    gemm_gi_tc_kernel<<<ggrid, 256>>>(x, Wi, bi, gi);

    // 2) persistent GRU scan (128 blocks, split-term accumulators)
    scan_kernel<<<SCAN_BLOCKS, SCAN_THREADS>>>(h0, Wh, bhn, out_h, out_ys);
}

// round 16
// speedup vs baseline: 1.1453x; 1.0428x over previous
#include <cuda_runtime.h>
#include <cuda_bf16.h>
#include <math.h>

// Problem constants
#define T_STEPS 512
#define BATCH   128
#define HDIM    512
#define HDIM3   1536

typedef unsigned long long u64;
typedef unsigned int u32;

// ---------------------------------------------------------------------------
// bf16 helpers
// ---------------------------------------------------------------------------
__device__ __forceinline__ u32 pkbf_(float f0, float f1) {
    unsigned short s0 = __bfloat16_as_ushort(__float2bfloat16_rn(f0));
    unsigned short s1 = __bfloat16_as_ushort(__float2bfloat16_rn(f1));
    return (u32)s0 | ((u32)s1 << 16);
}
__device__ __forceinline__ void split2_(float f0, float f1, u32& hi, u32& lo) {
    __nv_bfloat16 h0 = __float2bfloat16_rn(f0);
    __nv_bfloat16 h1 = __float2bfloat16_rn(f1);
    float r0 = f0 - __bfloat162float(h0);
    float r1 = f1 - __bfloat162float(h1);
    hi = (u32)__bfloat16_as_ushort(h0) | ((u32)__bfloat16_as_ushort(h1) << 16);
    lo = pkbf_(r0, r1);
}

// m16n8k16 bf16 MMA, fp32 accumulate.
__device__ __forceinline__ void mma_bf16(
    float& d0, float& d1, float& d2, float& d3,
    u32 a0, u32 a1, u32 a2, u32 a3, u32 b0, u32 b1)
{
    asm volatile(
        "mma.sync.aligned.m16n8k16.row.col.f32.bf16.bf16.f32 "
        "{%0,%1,%2,%3}, {%4,%5,%6,%7}, {%8,%9}, {%0,%1,%2,%3};"
        : "+f"(d0), "+f"(d1), "+f"(d2), "+f"(d3)
        : "r"(a0), "r"(a1), "r"(a2), "r"(a3), "r"(b0), "r"(b1));
}

// ---------------------------------------------------------------------------
// Scratch + dataflow-sync state: 32 arrival counters on separate 128B lines.
// Block bx signals counter (bx>>2) after each h write. A step proceeds when
// every counter reaches 4*(t+1). Counters are reset per launch.
// ---------------------------------------------------------------------------
#define KP_TOTAL 256   // 512 k / 2 per pair
#define NGRP 32
__device__ __align__(16) float g_gi[(size_t)T_STEPS * BATCH * HDIM3];
__device__ __align__(16) u64 g_h2[2][KP_TOTAL * BATCH];
__device__ __align__(128) u32 g_cnt[NGRP * 32];   // stride 32 u32 = 128 B

#define SCAN_BLOCKS 128

__global__ void reset_cnt_kernel() {
    if (threadIdx.x < NGRP) g_cnt[threadIdx.x * 32] = 0u;
}

// ---------------------------------------------------------------------------
// Pre-GEMM (bf16 3-term compensated MMA): gi = x @ Wi + bi.  (validated R13)
// ---------------------------------------------------------------------------
#define GSTRIDE 132

__global__ __launch_bounds__(256) void gemm_gi_tc_kernel(
    const float* __restrict__ X, const float* __restrict__ Wi,
    const float* __restrict__ bi, float* __restrict__ gi)
{
    __shared__ __align__(16) u64 Xs[8 * GSTRIDE];
    __shared__ __align__(16) u64 Ws[8 * GSTRIDE];

    const int m0 = blockIdx.y * 128;
    const int n0 = blockIdx.x * 128;
    const int tid = threadIdx.x;
    const int wid = tid >> 5;
    const int lane = tid & 31;
    const int g = lane >> 2;
    const int tig = lane & 3;
    const int wm = (wid & 3) * 32;
    const int wn = (wid >> 2) * 64;

    const int xr = tid >> 1;
    const int xc = (tid & 1) * 8;
    const int wkp = tid >> 5;
    const int nb = (lane) * 4;

    float acc[2][8][4];
#pragma unroll
    for (int mf = 0; mf < 2; mf++)
#pragma unroll
        for (int nf = 0; nf < 8; nf++)
#pragma unroll
            for (int r = 0; r < 4; r++) acc[mf][nf][r] = 0.f;

    for (int k0 = 0; k0 < HDIM; k0 += 16) {
#pragma unroll
        for (int h = 0; h < 2; h++) {
            float4 v = *(const float4*)&X[(size_t)(m0 + xr) * HDIM + k0 + xc + h * 4];
            u32 hi0, lo0, hi1, lo1;
            split2_(v.x, v.y, hi0, lo0);
            split2_(v.z, v.w, hi1, lo1);
            Xs[(xc / 2 + h * 2 + 0) * GSTRIDE + xr] = (u64)hi0 | ((u64)lo0 << 32);
            Xs[(xc / 2 + h * 2 + 1) * GSTRIDE + xr] = (u64)hi1 | ((u64)lo1 << 32);
        }
        {
            float4 r0 = *(const float4*)&Wi[(size_t)(k0 + 2 * wkp) * HDIM3 + n0 + nb];
            float4 r1 = *(const float4*)&Wi[(size_t)(k0 + 2 * wkp + 1) * HDIM3 + n0 + nb];
            float a0[4] = {r0.x, r0.y, r0.z, r0.w};
            float a1[4] = {r1.x, r1.y, r1.z, r1.w};
#pragma unroll
            for (int i = 0; i < 4; i++) {
                u32 hi, lo;
                split2_(a0[i], a1[i], hi, lo);
                Ws[wkp * GSTRIDE + nb + i] = (u64)hi | ((u64)lo << 32);
            }
        }
        __syncthreads();

        u32 ah[2][4], al[2][4];
#pragma unroll
        for (int mf = 0; mf < 2; mf++) {
            int mr = wm + mf * 16 + g;
            u64 d0 = Xs[tig * GSTRIDE + mr];
            u64 d1 = Xs[tig * GSTRIDE + mr + 8];
            u64 d2 = Xs[(tig + 4) * GSTRIDE + mr];
            u64 d3 = Xs[(tig + 4) * GSTRIDE + mr + 8];
            ah[mf][0] = (u32)d0; al[mf][0] = (u32)(d0 >> 32);
            ah[mf][1] = (u32)d1; al[mf][1] = (u32)(d1 >> 32);
            ah[mf][2] = (u32)d2; al[mf][2] = (u32)(d2 >> 32);
            ah[mf][3] = (u32)d3; al[mf][3] = (u32)(d3 >> 32);
        }
#pragma unroll
        for (int nf = 0; nf < 8; nf++) {
            int nc = wn + nf * 8 + g;
            u64 e0 = Ws[tig * GSTRIDE + nc];
            u64 e1 = Ws[(tig + 4) * GSTRIDE + nc];
            u32 bh0 = (u32)e0, bl0 = (u32)(e0 >> 32);
            u32 bh1 = (u32)e1, bl1 = (u32)(e1 >> 32);
#pragma unroll
            for (int mf = 0; mf < 2; mf++) {
                mma_bf16(acc[mf][nf][0], acc[mf][nf][1], acc[mf][nf][2], acc[mf][nf][3],
                         ah[mf][0], ah[mf][1], ah[mf][2], ah[mf][3], bh0, bh1);
                mma_bf16(acc[mf][nf][0], acc[mf][nf][1], acc[mf][nf][2], acc[mf][nf][3],
                         ah[mf][0], ah[mf][1], ah[mf][2], ah[mf][3], bl0, bl1);
                mma_bf16(acc[mf][nf][0], acc[mf][nf][1], acc[mf][nf][2], acc[mf][nf][3],
                         al[mf][0], al[mf][1], al[mf][2], al[mf][3], bh0, bh1);
            }
        }
        __syncthreads();
    }

#pragma unroll
    for (int mf = 0; mf < 2; mf++) {
#pragma unroll
        for (int nf = 0; nf < 8; nf++) {
            int n = n0 + wn + nf * 8 + 2 * tig;
            float b0v = bi[n], b1v = bi[n + 1];
            int mA = m0 + wm + mf * 16 + g;
            int mB = mA + 8;
            *(float2*)&gi[(size_t)mA * HDIM3 + n] =
                make_float2(acc[mf][nf][0] + b0v, acc[mf][nf][1] + b1v);
            *(float2*)&gi[(size_t)mB * HDIM3 + n] =
                make_float2(acc[mf][nf][2] + b0v, acc[mf][nf][3] + b1v);
        }
    }
}

// ---------------------------------------------------------------------------
// Persistent scan (R13 core; 128 blocks x 256 threads, shuffle gates).
// Sync: spread arrival counters + per-warp parallel poll (no central
// arrive/release barrier). Same bulk-sync semantics as the old barrier:
// step t proceeds only when all 32 counters >= 4*(t+1)  <=>  every block has
// published h_t. Two h buffers remain sufficient.
// ---------------------------------------------------------------------------
#define SCAN_THREADS 256
#define BS_STRIDE 20      // u64; conflict-free B-frag loads
#define PD 4              // prefetch depth (ring)

__device__ __forceinline__ float fast_sigmoid(float x) {
    return 1.0f / (1.0f + __expf(-x));
}
__device__ __forceinline__ float fast_tanh(float x) {
    return 2.0f / (1.0f + __expf(-2.0f * x)) - 1.0f;
}

// Per-warp parallel wait: lane i polls counter i until all >= thr.
__device__ __forceinline__ void wait_all_groups(unsigned thr, int lane) {
    const u32* fp = &g_cnt[lane * 32];
    unsigned v;
    asm volatile("ld.acquire.gpu.u32 %0, [%1];" : "=r"(v) : "l"(fp) : "memory");
    bool ok = (v >= thr);
    while (!__all_sync(0xFFFFFFFFu, ok)) {
        if (!ok) {
            __nanosleep(16);
            asm volatile("ld.acquire.gpu.u32 %0, [%1];"
                         : "=r"(v) : "l"(fp) : "memory");
            ok = (v >= thr);
        }
    }
}

__global__ __launch_bounds__(SCAN_THREADS) void scan_kernel(
    const float* __restrict__ h0, const float* __restrict__ Wh,
    const float* __restrict__ bhn,
    float* __restrict__ out_h, float* __restrict__ out_ys)
{
    __shared__ __align__(16) u64 Bs[KP_TOTAL * BS_STRIDE];   // 40 KB

    const int tid = threadIdx.x;
    const int wid = tid >> 5;
    const int lane = tid & 31;
    const int g = lane >> 2;
    const int tig = lane & 3;
    const int j0 = blockIdx.x * 4;
    u32* const my_cnt = &g_cnt[(blockIdx.x >> 2) * 32];

    // --- One-time: Wh slice -> bf16-split k-pair fragments in SMEM ---
    {
        int kp = tid;  // 256 threads, 256 k-pairs
#pragma unroll
        for (int n = 12; n < 16; n++) Bs[kp * BS_STRIDE + n] = 0ull;
        for (int c = 0; c < 12; c++) {
            int col = (c >> 2) * HDIM + j0 + (c & 3);
            float w0 = Wh[(size_t)(2 * kp) * HDIM3 + col];
            float w1 = Wh[(size_t)(2 * kp + 1) * HDIM3 + col];
            u32 hi, lo;
            split2_(w0, w1, hi, lo);
            Bs[kp * BS_STRIDE + c] = (u64)hi | ((u64)lo << 32);
        }
    }

    // Lane's gate assignment
    const int row = wid * 16 + g + ((tig & 2) << 2);  // +8 for tig>=2
    const int jc = (tig & 1) * 2;                     // col pair base (0 or 2)
    const int jcol = j0 + jc;
    const int kp_out = j0 / 2 + (tig & 1);

    float bn0 = bhn[jcol], bn1 = bhn[jcol + 1];
    float hn0, hn1;
    {
        float2 v = *(const float2*)&h0[(size_t)row * HDIM + jcol];
        hn0 = v.x; hn1 = v.y;
        u32 hi, lo;
        split2_(hn0, hn1, hi, lo);
        g_h2[0][kp_out * BATCH + row] = (u64)hi | ((u64)lo << 32);
    }
    __syncthreads();
    if (tid == 0) {
        unsigned d;
        asm volatile("atom.release.gpu.add.u32 %0, [%1], 1;"
                     : "=r"(d) : "l"(my_cnt) : "memory");
    }

    const int mbase = wid * 16;   // warp's batch-row base for MMA

    for (int t = 0; t < T_STEPS; t++) {
        const u64* __restrict__ hp = g_h2[t & 1];

        // gi loads first (independent of h) — DRAM latency hides behind wait
        const float* gip = &g_gi[((size_t)t * BATCH + row) * HDIM3 + jcol];
        float2 gr = *(const float2*)gip;
        float2 gz = *(const float2*)(gip + HDIM);
        float2 gn = *(const float2*)(gip + 2 * HDIM);

        // Wait for all blocks to have published h_t.
        wait_all_groups(4u * (unsigned)(t + 1), lane);

        float acc[2][4];
#pragma unroll
        for (int nf = 0; nf < 2; nf++)
#pragma unroll
            for (int r = 0; r < 4; r++) acc[nf][r] = 0.f;

        // A-frag prefetch ring, depth PD=4.
        u64 pa[PD][4];
#pragma unroll
        for (int p = 0; p < PD; p++) {
            int ix = (p * 8 + tig) * BATCH + mbase + g;
            pa[p][0] = hp[ix];       pa[p][1] = hp[ix + 8];
            pa[p][2] = hp[ix + 512]; pa[p][3] = hp[ix + 520];
        }

#pragma unroll 4
        for (int kt = 0; kt < 32; kt++) {
            const int s = kt & (PD - 1);
            u64 d0 = pa[s][0], d1 = pa[s][1], d2 = pa[s][2], d3 = pa[s][3];
            if (kt + PD < 32) {
                int ix = ((kt + PD) * 8 + tig) * BATCH + mbase + g;
                pa[s][0] = hp[ix];       pa[s][1] = hp[ix + 8];
                pa[s][2] = hp[ix + 512]; pa[s][3] = hp[ix + 520];
            }
            u32 ah0 = (u32)d0, al0 = (u32)(d0 >> 32);
            u32 ah1 = (u32)d1, al1 = (u32)(d1 >> 32);
            u32 ah2 = (u32)d2, al2 = (u32)(d2 >> 32);
            u32 ah3 = (u32)d3, al3 = (u32)(d3 >> 32);
#pragma unroll
            for (int nf = 0; nf < 2; nf++) {
                u64 e0 = Bs[(kt * 8 + tig) * BS_STRIDE + nf * 8 + g];
                u64 e1 = Bs[(kt * 8 + tig + 4) * BS_STRIDE + nf * 8 + g];
                u32 bh0 = (u32)e0, bl0 = (u32)(e0 >> 32);
                u32 bh1 = (u32)e1, bl1 = (u32)(e1 >> 32);
                mma_bf16(acc[nf][0], acc[nf][1], acc[nf][2], acc[nf][3],
                         ah0, ah1, ah2, ah3, bh0, bh1);
                mma_bf16(acc[nf][0], acc[nf][1], acc[nf][2], acc[nf][3],
                         ah0, ah1, ah2, ah3, bl0, bl1);
                mma_bf16(acc[nf][0], acc[nf][1], acc[nf][2], acc[nf][3],
                         al0, al1, al2, al3, bh0, bh1);
            }
        }

        // Fragment exchange: partner lane = lane XOR 2 (tig0<->tig2, 1<->3).
        float sh0[4], sh1[4];
#pragma unroll
        for (int c = 0; c < 4; c++) {
            sh0[c] = __shfl_xor_sync(0xFFFFFFFFu, acc[0][c], 2);
            sh1[c] = __shfl_xor_sync(0xFFFFFFFFu, acc[1][c], 2);
        }

        float rin0, rin1, zin0, zin1, nin0, nin1;
        if ((tig & 2) == 0) {
            rin0 = acc[0][0]; rin1 = acc[0][1];
            zin0 = sh0[0];    zin1 = sh0[1];
            nin0 = acc[1][0]; nin1 = acc[1][1];
        } else {
            rin0 = sh0[2];    rin1 = sh0[3];
            zin0 = acc[0][2]; zin1 = acc[0][3];
            nin0 = sh1[2];    nin1 = sh1[3];
        }

        {
            float r0 = fast_sigmoid(gr.x + rin0);
            float r1 = fast_sigmoid(gr.y + rin1);
            float z0 = fast_sigmoid(gz.x + zin0);
            float z1 = fast_sigmoid(gz.y + zin1);
            float n0 = fast_tanh(gn.x + r0 * (nin0 + bn0));
            float n1 = fast_tanh(gn.y + r1 * (nin1 + bn1));
            hn0 = (1.0f - z0) * n0 + z0 * hn0;
            hn1 = (1.0f - z1) * n1 + z1 * hn1;
        }

        *(float2*)&out_ys[((size_t)t * BATCH + row) * HDIM + jcol] =
            make_float2(hn0, hn1);

        {
            u64* __restrict__ hq = g_h2[(t & 1) ^ 1];
            u32 hi, lo;
            split2_(hn0, hn1, hi, lo);
            hq[kp_out * BATCH + row] = (u64)hi | ((u64)lo << 32);
        }

        // Publish h_{t+1}: all threads' writes done -> signal group counter.
        __syncthreads();
        if (tid == 0) {
            unsigned d;
            asm volatile("atom.release.gpu.add.u32 %0, [%1], 1;"
                         : "=r"(d) : "l"(my_cnt) : "memory");
        }
    }

    if (out_h) {
        *(float2*)&out_h[(size_t)row * HDIM + jcol] = make_float2(hn0, hn1);
    }
}

// ---------------------------------------------------------------------------
// kernel_launch: inputs per metadata order: x, h0, Wi, bi, Wh, bhn
// ---------------------------------------------------------------------------
extern "C" void kernel_launch(void* const* d_in, const int* in_sizes, int n_in,
                              void* d_out, int out_size)
{
    const float* x   = (const float*)d_in[0];   // [T, B, H]
    const float* h0  = (const float*)d_in[1];   // [B, H]
    const float* Wi  = (const float*)d_in[2];   // [H, 3H]
    const float* bi  = (const float*)d_in[3];   // [3H]
    const float* Wh  = (const float*)d_in[4];   // [H, 3H]
    const float* bhn = (const float*)d_in[5];   // [H]

    float* out = (float*)d_out;
    float* out_h;
    float* out_ys;
    const long long ys_elems = (long long)T_STEPS * BATCH * HDIM;
    if ((long long)out_size >= ys_elems + (long long)BATCH * HDIM) {
        out_h = out;                    // (h_final, ys) flattened in order
        out_ys = out + (size_t)BATCH * HDIM;
    } else {
        out_h = nullptr;                // ys only
        out_ys = out;
    }

    float* gi;
    cudaGetSymbolAddress((void**)&gi, g_gi);

    // 0) reset arrival counters (graph-replay safe)
    reset_cnt_kernel<<<1, 32>>>();

    // 1) gi = x @ Wi + bi  (bf16 3-term compensated tensor-core GEMM)
    dim3 ggrid(HDIM3 / 128, (T_STEPS * BATCH) / 128);
    gemm_gi_tc_kernel<<<ggrid, 256>>>(x, Wi, bi, gi);

    // 2) persistent GRU scan (spread-counter dataflow sync)
    scan_kernel<<<SCAN_BLOCKS, SCAN_THREADS>>>(h0, Wh, bhn, out_h, out_ys);
}

// round 17
// speedup vs baseline: 1.1943x; 1.0428x over previous
#include <cuda_runtime.h>
#include <cuda_bf16.h>
#include <math.h>

// Problem constants
#define T_STEPS 512
#define BATCH   128
#define HDIM    512
#define HDIM3   1536

typedef unsigned long long u64;
typedef unsigned int u32;

// ---------------------------------------------------------------------------
// bf16 helpers
// ---------------------------------------------------------------------------
__device__ __forceinline__ u32 pkbf_(float f0, float f1) {
    unsigned short s0 = __bfloat16_as_ushort(__float2bfloat16_rn(f0));
    unsigned short s1 = __bfloat16_as_ushort(__float2bfloat16_rn(f1));
    return (u32)s0 | ((u32)s1 << 16);
}
__device__ __forceinline__ void split2_(float f0, float f1, u32& hi, u32& lo) {
    __nv_bfloat16 h0 = __float2bfloat16_rn(f0);
    __nv_bfloat16 h1 = __float2bfloat16_rn(f1);
    float r0 = f0 - __bfloat162float(h0);
    float r1 = f1 - __bfloat162float(h1);
    hi = (u32)__bfloat16_as_ushort(h0) | ((u32)__bfloat16_as_ushort(h1) << 16);
    lo = pkbf_(r0, r1);
}

// m16n8k16 bf16 MMA, fp32 accumulate.
__device__ __forceinline__ void mma_bf16(
    float& d0, float& d1, float& d2, float& d3,
    u32 a0, u32 a1, u32 a2, u32 a3, u32 b0, u32 b1)
{
    asm volatile(
        "mma.sync.aligned.m16n8k16.row.col.f32.bf16.bf16.f32 "
        "{%0,%1,%2,%3}, {%4,%5,%6,%7}, {%8,%9}, {%0,%1,%2,%3};"
        : "+f"(d0), "+f"(d1), "+f"(d2), "+f"(d3)
        : "r"(a0), "r"(a1), "r"(a2), "r"(a3), "r"(b0), "r"(b1));
}

// ---------------------------------------------------------------------------
// Scratch + sync state.
// g_cnt: 32 spread arrival counters (4 blocks each) for "h_t fully published".
// g_pflag[128]: per-block partial-ready flag (value = completed steps).
// g_part: per-block partial gh dump (256 lanes x 12 floats).
// ---------------------------------------------------------------------------
#define KP_TOTAL 256   // 512 k / 2 per pair
#define NGRP 32
__device__ __align__(16) float g_gi[(size_t)T_STEPS * BATCH * HDIM3];
__device__ __align__(16) u64 g_h2[2][KP_TOTAL * BATCH];
__device__ __align__(128) u32 g_cnt[NGRP * 32];     // stride 32 u32 = 128 B
__device__ __align__(128) u32 g_pflag[128 * 32];    // stride 32 u32 = 128 B
__device__ __align__(16) float g_part[(size_t)128 * 3072];

#define SCAN_BLOCKS 128

__global__ void reset_cnt_kernel() {
    int t = threadIdx.x;
    if (t < NGRP) g_cnt[t * 32] = 0u;
    if (t < 128) g_pflag[t * 32] = 0u;
}

// ---------------------------------------------------------------------------
// Pre-GEMM (bf16 3-term compensated MMA): gi = x @ Wi + bi.  (validated R13)
// ---------------------------------------------------------------------------
#define GSTRIDE 132

__global__ __launch_bounds__(256) void gemm_gi_tc_kernel(
    const float* __restrict__ X, const float* __restrict__ Wi,
    const float* __restrict__ bi, float* __restrict__ gi)
{
    __shared__ __align__(16) u64 Xs[8 * GSTRIDE];
    __shared__ __align__(16) u64 Ws[8 * GSTRIDE];

    const int m0 = blockIdx.y * 128;
    const int n0 = blockIdx.x * 128;
    const int tid = threadIdx.x;
    const int wid = tid >> 5;
    const int lane = tid & 31;
    const int g = lane >> 2;
    const int tig = lane & 3;
    const int wm = (wid & 3) * 32;
    const int wn = (wid >> 2) * 64;

    const int xr = tid >> 1;
    const int xc = (tid & 1) * 8;
    const int wkp = tid >> 5;
    const int nb = (lane) * 4;

    float acc[2][8][4];
#pragma unroll
    for (int mf = 0; mf < 2; mf++)
#pragma unroll
        for (int nf = 0; nf < 8; nf++)
#pragma unroll
            for (int r = 0; r < 4; r++) acc[mf][nf][r] = 0.f;

    for (int k0 = 0; k0 < HDIM; k0 += 16) {
#pragma unroll
        for (int h = 0; h < 2; h++) {
            float4 v = *(const float4*)&X[(size_t)(m0 + xr) * HDIM + k0 + xc + h * 4];
            u32 hi0, lo0, hi1, lo1;
            split2_(v.x, v.y, hi0, lo0);
            split2_(v.z, v.w, hi1, lo1);
            Xs[(xc / 2 + h * 2 + 0) * GSTRIDE + xr] = (u64)hi0 | ((u64)lo0 << 32);
            Xs[(xc / 2 + h * 2 + 1) * GSTRIDE + xr] = (u64)hi1 | ((u64)lo1 << 32);
        }
        {
            float4 r0 = *(const float4*)&Wi[(size_t)(k0 + 2 * wkp) * HDIM3 + n0 + nb];
            float4 r1 = *(const float4*)&Wi[(size_t)(k0 + 2 * wkp + 1) * HDIM3 + n0 + nb];
            float a0[4] = {r0.x, r0.y, r0.z, r0.w};
            float a1[4] = {r1.x, r1.y, r1.z, r1.w};
#pragma unroll
            for (int i = 0; i < 4; i++) {
                u32 hi, lo;
                split2_(a0[i], a1[i], hi, lo);
                Ws[wkp * GSTRIDE + nb + i] = (u64)hi | ((u64)lo << 32);
            }
        }
        __syncthreads();

        u32 ah[2][4], al[2][4];
#pragma unroll
        for (int mf = 0; mf < 2; mf++) {
            int mr = wm + mf * 16 + g;
            u64 d0 = Xs[tig * GSTRIDE + mr];
            u64 d1 = Xs[tig * GSTRIDE + mr + 8];
            u64 d2 = Xs[(tig + 4) * GSTRIDE + mr];
            u64 d3 = Xs[(tig + 4) * GSTRIDE + mr + 8];
            ah[mf][0] = (u32)d0; al[mf][0] = (u32)(d0 >> 32);
            ah[mf][1] = (u32)d1; al[mf][1] = (u32)(d1 >> 32);
            ah[mf][2] = (u32)d2; al[mf][2] = (u32)(d2 >> 32);
            ah[mf][3] = (u32)d3; al[mf][3] = (u32)(d3 >> 32);
        }
#pragma unroll
        for (int nf = 0; nf < 8; nf++) {
            int nc = wn + nf * 8 + g;
            u64 e0 = Ws[tig * GSTRIDE + nc];
            u64 e1 = Ws[(tig + 4) * GSTRIDE + nc];
            u32 bh0 = (u32)e0, bl0 = (u32)(e0 >> 32);
            u32 bh1 = (u32)e1, bl1 = (u32)(e1 >> 32);
#pragma unroll
            for (int mf = 0; mf < 2; mf++) {
                mma_bf16(acc[mf][nf][0], acc[mf][nf][1], acc[mf][nf][2], acc[mf][nf][3],
                         ah[mf][0], ah[mf][1], ah[mf][2], ah[mf][3], bh0, bh1);
                mma_bf16(acc[mf][nf][0], acc[mf][nf][1], acc[mf][nf][2], acc[mf][nf][3],
                         ah[mf][0], ah[mf][1], ah[mf][2], ah[mf][3], bl0, bl1);
                mma_bf16(acc[mf][nf][0], acc[mf][nf][1], acc[mf][nf][2], acc[mf][nf][3],
                         al[mf][0], al[mf][1], al[mf][2], al[mf][3], bh0, bh1);
            }
        }
        __syncthreads();
    }

#pragma unroll
    for (int mf = 0; mf < 2; mf++) {
#pragma unroll
        for (int nf = 0; nf < 8; nf++) {
            int n = n0 + wn + nf * 8 + 2 * tig;
            float b0v = bi[n], b1v = bi[n + 1];
            int mA = m0 + wm + mf * 16 + g;
            int mB = mA + 8;
            *(float2*)&gi[(size_t)mA * HDIM3 + n] =
                make_float2(acc[mf][nf][0] + b0v, acc[mf][nf][1] + b1v);
            *(float2*)&gi[(size_t)mB * HDIM3 + n] =
                make_float2(acc[mf][nf][2] + b0v, acc[mf][nf][3] + b1v);
        }
    }
}

// ---------------------------------------------------------------------------
// Persistent scan, k-split pairs: 128 blocks = 64 pairs x 2 k-halves.
// Pair p owns h-cols 8p..8p+7 (24 gate cols = 3 n-frags, R14 lane-local
// layout: nf0=r, nf1=z, nf2=n; lane (g,tig) holds rows rA/rB, cols 2tig+).
// Block 2p+kh reduces k in [kh*256, kh*256+256) (128 kp) -> reads HALF of h.
// Partials exchanged via L2 (release flag / acquire poll); both blocks sum
// and compute gates; each stores its own 64-row half of ys and h.
// ---------------------------------------------------------------------------
#define SCAN_THREADS 256
#define BS_STRIDE 28      // u64; conflict-free B-frag loads (128 kp -> 28 KB)
#define PD 4              // prefetch depth (ring)

__device__ __forceinline__ float fast_sigmoid(float x) {
    return 1.0f / (1.0f + __expf(-x));
}
__device__ __forceinline__ float fast_tanh(float x) {
    return 2.0f / (1.0f + __expf(-2.0f * x)) - 1.0f;
}

// Per-warp parallel wait: lane i polls counter i until all >= thr.
__device__ __forceinline__ void wait_all_groups(unsigned thr, int lane) {
    const u32* fp = &g_cnt[lane * 32];
    unsigned v;
    asm volatile("ld.acquire.gpu.u32 %0, [%1];" : "=r"(v) : "l"(fp) : "memory");
    bool ok = (v >= thr);
    while (!__all_sync(0xFFFFFFFFu, ok)) {
        if (!ok) {
            __nanosleep(16);
            asm volatile("ld.acquire.gpu.u32 %0, [%1];"
                         : "=r"(v) : "l"(fp) : "memory");
            ok = (v >= thr);
        }
    }
}

__global__ __launch_bounds__(SCAN_THREADS) void scan_kernel(
    const float* __restrict__ h0, const float* __restrict__ Wh,
    const float* __restrict__ bhn,
    float* __restrict__ out_h, float* __restrict__ out_ys)
{
    __shared__ __align__(16) u64 Bs[128 * BS_STRIDE];   // 28 KB

    const int tid = threadIdx.x;
    const int wid = tid >> 5;
    const int lane = tid & 31;
    const int g = lane >> 2;
    const int tig = lane & 3;
    const int bx = blockIdx.x;
    const int pair = bx >> 1;
    const int khalf = bx & 1;
    const int j0 = pair * 8;
    const int kp_base = khalf * 128;       // this block's kp half
    u32* const my_cnt = &g_cnt[(bx >> 2) * 32];
    u32* const my_pflag = &g_pflag[bx * 32];
    u32* const partner_pflag = &g_pflag[(bx ^ 1) * 32];
    float* const my_part = &g_part[(size_t)bx * 3072];
    const float* const partner_part = &g_part[(size_t)(bx ^ 1) * 3072];

    // --- One-time: Wh slice (my k-half) -> bf16-split k-pair frags in SMEM --
    for (int kp = tid; kp < 128; kp += SCAN_THREADS) {
        for (int c = 0; c < 24; c++) {
            int col = (c >> 3) * HDIM + j0 + (c & 7);
            float w0 = Wh[(size_t)(2 * (kp_base + kp)) * HDIM3 + col];
            float w1 = Wh[(size_t)(2 * (kp_base + kp) + 1) * HDIM3 + col];
            u32 hi, lo;
            split2_(w0, w1, hi, lo);
            Bs[kp * BS_STRIDE + c] = (u64)hi | ((u64)lo << 32);
        }
    }

    // Lane's assignment: rows rA = wid*16+g, rB = rA+8; cols jcol..jcol+1.
    const int mbase = wid * 16;
    const int rA = mbase + g;
    const int rB = rA + 8;
    const int jcol = j0 + 2 * tig;
    const int kp_out = j0 / 2 + tig;
    const bool mine = ((wid >> 2) == khalf);   // rows in [khalf*64, +64)

    float bn0 = bhn[jcol], bn1 = bhn[jcol + 1];
    float hA0, hA1, hB0, hB1;
    {
        float2 vA = *(const float2*)&h0[(size_t)rA * HDIM + jcol];
        float2 vB = *(const float2*)&h0[(size_t)rB * HDIM + jcol];
        hA0 = vA.x; hA1 = vA.y; hB0 = vB.x; hB1 = vB.y;
        if (mine) {
            u32 hi, lo;
            split2_(hA0, hA1, hi, lo);
            g_h2[0][kp_out * BATCH + rA] = (u64)hi | ((u64)lo << 32);
            split2_(hB0, hB1, hi, lo);
            g_h2[0][kp_out * BATCH + rB] = (u64)hi | ((u64)lo << 32);
        }
    }
    __syncthreads();
    if (tid == 0) {
        unsigned d;
        asm volatile("atom.release.gpu.add.u32 %0, [%1], 1;"
                     : "=r"(d) : "l"(my_cnt) : "memory");
    }

    for (int t = 0; t < T_STEPS; t++) {
        const u64* __restrict__ hp = g_h2[t & 1];

        // gi loads first (independent of h) — DRAM latency hides behind wait
        const float* giA = &g_gi[((size_t)t * BATCH + rA) * HDIM3 + jcol];
        const float* giB = &g_gi[((size_t)t * BATCH + rB) * HDIM3 + jcol];
        float2 grA = *(const float2*)giA;
        float2 gzA = *(const float2*)(giA + HDIM);
        float2 gnA = *(const float2*)(giA + 2 * HDIM);
        float2 grB = *(const float2*)giB;
        float2 gzB = *(const float2*)(giB + HDIM);
        float2 gnB = *(const float2*)(giB + 2 * HDIM);

        // Wait for all blocks to have published h_t.
        wait_all_groups(4u * (unsigned)(t + 1), lane);

        float acc[3][4];
#pragma unroll
        for (int nf = 0; nf < 3; nf++)
#pragma unroll
            for (int r = 0; r < 4; r++) acc[nf][r] = 0.f;

        // A-frag prefetch ring over my 16 kt (kp in [kp_base, kp_base+128)).
        u64 pa[PD][4];
#pragma unroll
        for (int p = 0; p < PD; p++) {
            int ix = (kp_base + p * 8 + tig) * BATCH + mbase + g;
            pa[p][0] = hp[ix];       pa[p][1] = hp[ix + 8];
            pa[p][2] = hp[ix + 512]; pa[p][3] = hp[ix + 520];
        }

#pragma unroll 4
        for (int kt = 0; kt < 16; kt++) {
            const int s = kt & (PD - 1);
            u64 d0 = pa[s][0], d1 = pa[s][1], d2 = pa[s][2], d3 = pa[s][3];
            if (kt + PD < 16) {
                int ix = (kp_base + (kt + PD) * 8 + tig) * BATCH + mbase + g;
                pa[s][0] = hp[ix];       pa[s][1] = hp[ix + 8];
                pa[s][2] = hp[ix + 512]; pa[s][3] = hp[ix + 520];
            }
            u32 ah0 = (u32)d0, al0 = (u32)(d0 >> 32);
            u32 ah1 = (u32)d1, al1 = (u32)(d1 >> 32);
            u32 ah2 = (u32)d2, al2 = (u32)(d2 >> 32);
            u32 ah3 = (u32)d3, al3 = (u32)(d3 >> 32);
#pragma unroll
            for (int nf = 0; nf < 3; nf++) {
                u64 e0 = Bs[(kt * 8 + tig) * BS_STRIDE + nf * 8 + g];
                u64 e1 = Bs[(kt * 8 + tig + 4) * BS_STRIDE + nf * 8 + g];
                u32 bh0 = (u32)e0, bl0 = (u32)(e0 >> 32);
                u32 bh1 = (u32)e1, bl1 = (u32)(e1 >> 32);
                mma_bf16(acc[nf][0], acc[nf][1], acc[nf][2], acc[nf][3],
                         ah0, ah1, ah2, ah3, bh0, bh1);
                mma_bf16(acc[nf][0], acc[nf][1], acc[nf][2], acc[nf][3],
                         ah0, ah1, ah2, ah3, bl0, bl1);
                mma_bf16(acc[nf][0], acc[nf][1], acc[nf][2], acc[nf][3],
                         al0, al1, al2, al3, bh0, bh1);
            }
        }

        // Publish my partial (12 floats/lane) and signal.
        {
            float4* pp = (float4*)(my_part + tid * 12);
            pp[0] = make_float4(acc[0][0], acc[0][1], acc[0][2], acc[0][3]);
            pp[1] = make_float4(acc[1][0], acc[1][1], acc[1][2], acc[1][3]);
            pp[2] = make_float4(acc[2][0], acc[2][1], acc[2][2], acc[2][3]);
        }
        __syncthreads();
        if (tid == 0) {
            unsigned d;
            asm volatile("atom.release.gpu.add.u32 %0, [%1], 1;"
                         : "=r"(d) : "l"(my_pflag) : "memory");
            // Wait for partner's partial of this step.
            unsigned v;
            while (1) {
                asm volatile("ld.acquire.gpu.u32 %0, [%1];"
                             : "=r"(v) : "l"(partner_pflag) : "memory");
                if (v >= (unsigned)(t + 1)) break;
                __nanosleep(16);
            }
        }
        __syncthreads();

        // Sum partner partial.
        {
            const float4* pp = (const float4*)(partner_part + tid * 12);
            float4 q0 = pp[0], q1 = pp[1], q2 = pp[2];
            acc[0][0] += q0.x; acc[0][1] += q0.y; acc[0][2] += q0.z; acc[0][3] += q0.w;
            acc[1][0] += q1.x; acc[1][1] += q1.y; acc[1][2] += q1.z; acc[1][3] += q1.w;
            acc[2][0] += q2.x; acc[2][1] += q2.y; acc[2][2] += q2.z; acc[2][3] += q2.w;
        }

        // Lane-local gates (R14 layout): acc[0]=r, acc[1]=z, acc[2]=n;
        // c0/c1 = row rA, c2/c3 = row rB.
        {
            float r0 = fast_sigmoid(grA.x + acc[0][0]);
            float r1 = fast_sigmoid(grA.y + acc[0][1]);
            float z0 = fast_sigmoid(gzA.x + acc[1][0]);
            float z1 = fast_sigmoid(gzA.y + acc[1][1]);
            float n0 = fast_tanh(gnA.x + r0 * (acc[2][0] + bn0));
            float n1 = fast_tanh(gnA.y + r1 * (acc[2][1] + bn1));
            hA0 = (1.0f - z0) * n0 + z0 * hA0;
            hA1 = (1.0f - z1) * n1 + z1 * hA1;
        }
        {
            float r0 = fast_sigmoid(grB.x + acc[0][2]);
            float r1 = fast_sigmoid(grB.y + acc[0][3]);
            float z0 = fast_sigmoid(gzB.x + acc[1][2]);
            float z1 = fast_sigmoid(gzB.y + acc[1][3]);
            float n0 = fast_tanh(gnB.x + r0 * (acc[2][2] + bn0));
            float n1 = fast_tanh(gnB.y + r1 * (acc[2][3] + bn1));
            hB0 = (1.0f - z0) * n0 + z0 * hB0;
            hB1 = (1.0f - z1) * n1 + z1 * hB1;
        }

        if (mine) {
            *(float2*)&out_ys[((size_t)t * BATCH + rA) * HDIM + jcol] =
                make_float2(hA0, hA1);
            *(float2*)&out_ys[((size_t)t * BATCH + rB) * HDIM + jcol] =
                make_float2(hB0, hB1);

            u64* __restrict__ hq = g_h2[(t & 1) ^ 1];
            u32 hi, lo;
            split2_(hA0, hA1, hi, lo);
            hq[kp_out * BATCH + rA] = (u64)hi | ((u64)lo << 32);
            split2_(hB0, hB1, hi, lo);
            hq[kp_out * BATCH + rB] = (u64)hi | ((u64)lo << 32);
        }

        // Publish h_{t+1}: signal group counter.
        __syncthreads();
        if (tid == 0) {
            unsigned d;
            asm volatile("atom.release.gpu.add.u32 %0, [%1], 1;"
                         : "=r"(d) : "l"(my_cnt) : "memory");
        }
    }

    if (out_h && mine) {
        *(float2*)&out_h[(size_t)rA * HDIM + jcol] = make_float2(hA0, hA1);
        *(float2*)&out_h[(size_t)rB * HDIM + jcol] = make_float2(hB0, hB1);
    }
}

// ---------------------------------------------------------------------------
// kernel_launch: inputs per metadata order: x, h0, Wi, bi, Wh, bhn
// ---------------------------------------------------------------------------
extern "C" void kernel_launch(void* const* d_in, const int* in_sizes, int n_in,
                              void* d_out, int out_size)
{
    const float* x   = (const float*)d_in[0];   // [T, B, H]
    const float* h0  = (const float*)d_in[1];   // [B, H]
    const float* Wi  = (const float*)d_in[2];   // [H, 3H]
    const float* bi  = (const float*)d_in[3];   // [3H]
    const float* Wh  = (const float*)d_in[4];   // [H, 3H]
    const float* bhn = (const float*)d_in[5];   // [H]

    float* out = (float*)d_out;
    float* out_h;
    float* out_ys;
    const long long ys_elems = (long long)T_STEPS * BATCH * HDIM;
    if ((long long)out_size >= ys_elems + (long long)BATCH * HDIM) {
        out_h = out;                    // (h_final, ys) flattened in order
        out_ys = out + (size_t)BATCH * HDIM;
    } else {
        out_h = nullptr;                // ys only
        out_ys = out;
    }

    float* gi;
    cudaGetSymbolAddress((void**)&gi, g_gi);

    // 0) reset sync state (graph-replay safe)
    reset_cnt_kernel<<<1, 128>>>();

    // 1) gi = x @ Wi + bi  (bf16 3-term compensated tensor-core GEMM)
    dim3 ggrid(HDIM3 / 128, (T_STEPS * BATCH) / 128);
    gemm_gi_tc_kernel<<<ggrid, 256>>>(x, Wi, bi, gi);

    // 2) persistent GRU scan (k-split pairs; halved h-read per block)
    scan_kernel<<<SCAN_BLOCKS, SCAN_THREADS>>>(h0, Wh, bhn, out_h, out_ys);
}